// round 7
// baseline (speedup 1.0000x reference)
#include <cuda_runtime.h>

#define NCH   128
#define BATCH 16384
#define GRIDB 2048
#define RPB   (BATCH / GRIDB)    // 8 rows per block, stride GRIDB

// ---------------------------------------------------------------------------
// Coupling table (lo, l1, l2) in the reference enumeration order
// ---------------------------------------------------------------------------
__host__ __device__ constexpr int cpl_lo(int c){ constexpr int t[18]={0,0,0,1,1,1,1,1,1,2,2,2,2,2,2,3,3,3}; return t[c]; }
__host__ __device__ constexpr int cpl_l1(int c){ constexpr int t[18]={0,1,2,0,1,1,1,2,2,0,1,1,2,2,2,1,2,2}; return t[c]; }
__host__ __device__ constexpr int cpl_l2(int c){ constexpr int t[18]={0,1,2,1,0,1,2,1,2,2,1,2,0,1,2,2,1,2}; return t[c]; }

// ---------------------------------------------------------------------------
// Compile-time CG table (constexpr port of reference, double precision, 0.5
// folded in). Every nonzero becomes an FFMA/FMUL immediate in SASS.
// ---------------------------------------------------------------------------
__host__ __device__ constexpr double cfabs_c(double x){ return x < 0 ? -x : x; }
__host__ __device__ constexpr double csqrt_c(double x){
    double g = x > 1.0 ? x : 1.0;
    for(int i=0;i<64;i++) g = 0.5*(g + x/g);
    return g;
}
__host__ __device__ constexpr double fct_c(int n){ double r = 1.0; for(int i=2;i<=n;i++) r *= (double)i; return r; }

struct Cplx { double re, im; };
__host__ __device__ constexpr Cplx cmul(Cplx a, Cplx b){ return Cplx{a.re*b.re - a.im*b.im, a.re*b.im + a.im*b.re}; }
__host__ __device__ constexpr Cplx cadd(Cplx a, Cplx b){ return Cplx{a.re + b.re, a.im + b.im}; }
__host__ __device__ constexpr Cplx cconj(Cplx a){ return Cplx{a.re, -a.im}; }
__host__ __device__ constexpr Cplx cscal(double s, Cplx a){ return Cplx{s*a.re, s*a.im}; }

struct CgTable { float v[18][5][5][7]; };

__host__ __device__ constexpr CgTable build_cg_table(){
    CgTable T{};
    for(int c=0;c<18;c++){
        const int lo = cpl_lo(c), l1 = cpl_l1(c), l2 = cpl_l2(c);

        double C[7][7][7] = {};
        {
            double pref_j = csqrt_c((2*lo+1) * fct_c(lo+l1-l2) * fct_c(lo-l1+l2) *
                                    fct_c(l1+l2-lo) / fct_c(l1+l2+lo+1));
            for(int m1=-l1;m1<=l1;m1++){
                for(int m2=-l2;m2<=l2;m2++){
                    int m3 = m1 + m2;
                    if(m3 < -lo || m3 > lo) continue;
                    double pref_m = csqrt_c(fct_c(lo+m3)*fct_c(lo-m3)*fct_c(l1-m1)*
                                            fct_c(l1+m1)*fct_c(l2-m2)*fct_c(l2+m2));
                    double s = 0.0;
                    for(int vv=0; vv<=l1+l2-lo; vv++){
                        int a = l1+l2-lo-vv, b = l1-m1-vv, cc = l2+m2-vv;
                        int d = lo-l2+m1+vv, e = lo-l1-m2+vv;
                        if(a<0 || b<0 || cc<0 || d<0 || e<0) continue;
                        double term = 1.0 / (fct_c(vv)*fct_c(a)*fct_c(b)*fct_c(cc)*fct_c(d)*fct_c(e));
                        s += (vv & 1) ? -term : term;
                    }
                    C[m1+l1][m2+l2][m3+lo] = pref_j * pref_m * s;
                }
            }
        }

        Cplx q[3][7][7] = {};
        const int ls[3] = {l1, l2, lo};
        for(int t=0;t<3;t++){
            const int l = ls[t];
            const double s2 = 1.0 / csqrt_c(2.0);
            for(int m=-l;m<0;m++){
                q[t][l+m][l-m] = Cplx{s2, 0.0};
                q[t][l+m][l+m] = Cplx{0.0, -s2};
            }
            q[t][l][l] = Cplx{1.0, 0.0};
            for(int m=1;m<=l;m++){
                double sg = (m & 1) ? -1.0 : 1.0;
                q[t][l+m][l+m] = Cplx{sg*s2, 0.0};
                q[t][l+m][l-m] = Cplx{0.0, sg*s2};
            }
            Cplx ph = (l==0) ? Cplx{1,0} : (l==1) ? Cplx{0,-1} : (l==2) ? Cplx{-1,0} : Cplx{0,1};
            for(int a=0;a<7;a++) for(int b=0;b<7;b++) q[t][a][b] = cmul(q[t][a][b], ph);
        }

        const int d1 = 2*l1+1, d2 = 2*l2+1, d3 = 2*lo+1;
        double Rre[5][5][7] = {}, Rim[5][5][7] = {};
        double sre = 0.0, sim = 0.0;
        for(int i=0;i<d1;i++)
            for(int j=0;j<d2;j++)
                for(int k=0;k<d3;k++){
                    Cplx s{0.0, 0.0};
                    for(int a=0;a<d1;a++)
                        for(int b=0;b<d2;b++)
                            for(int cc=0;cc<d3;cc++){
                                if(C[a][b][cc] == 0.0) continue;
                                s = cadd(s, cscal(C[a][b][cc],
                                        cmul(cmul(q[0][a][i], q[1][b][j]), cconj(q[2][cc][k]))));
                            }
                    Rre[i][j][k] = s.re; Rim[i][j][k] = s.im;
                    sre += cfabs_c(s.re); sim += cfabs_c(s.im);
                }
        const bool use_re = (sre >= sim);
        for(int i=0;i<d1;i++)
            for(int j=0;j<d2;j++)
                for(int k=0;k<d3;k++){
                    double val = use_re ? Rre[i][j][k] : Rim[i][j][k];
                    T.v[c][i][j][k] = 0.5f * (float)val;
                }
    }
    return T;
}

constexpr CgTable CG = build_cg_table();

// ---------------------------------------------------------------------------
// Compile-time helpers: symmetric folding, first-nonzero detection
// ---------------------------------------------------------------------------
__host__ __device__ constexpr int tri_i(int d, int t){
    int i = 0, rem = t;
    while(rem >= d - i){ rem -= d - i; i++; }
    return i;
}
__host__ __device__ constexpr int tri_j(int d, int t){
    int i = 0, rem = t;
    while(rem >= d - i){ rem -= d - i; i++; }
    return i + rem;
}

__host__ __device__ constexpr float cg_symv(int c, int i, int j, int k){
    return (i == j) ? CG.v[c][i][j][k] : (CG.v[c][i][j][k] + CG.v[c][j][i][k]);
}

__host__ __device__ constexpr int first_nz_asym(int c, int K){
    const int d1 = 2*cpl_l1(c)+1, d2 = 2*cpl_l2(c)+1, d3 = 2*cpl_lo(c)+1;
    for(int i=0;i<d1;i++)
        for(int j=0;j<d2;j++)
            if(CG.v[c][i][j][K] != 0.0f) return (i*d2+j)*d3 + K;
    return -1;
}
__host__ __device__ constexpr int first_nz_sym(int c, int K){
    const int d = 2*cpl_l1(c)+1;
    int t = 0;
    for(int i=0;i<d;i++)
        for(int j=i;j<d;j++,t++)
            if(cg_symv(c,i,j,K) != 0.0f) return t;
    return -1;
}
__host__ __device__ constexpr bool cpl_any(int c, bool sym){
    const int d3 = 2*cpl_lo(c)+1;
    for(int k=0;k<d3;k++)
        if((sym ? first_nz_sym(c,k) : first_nz_asym(c,k)) >= 0) return true;
    return false;
}

// ---------------------------------------------------------------------------
// Unrolled contraction loops (template recursion, all indices compile-time)
// ---------------------------------------------------------------------------
template<int C, bool TRANS, int N, int TOTAL>
struct ALoop {
    __device__ __forceinline__ static void run(const float* __restrict__ p, float* tp){
        constexpr int D1 = 2*cpl_l1(C)+1, D2 = 2*cpl_l2(C)+1, D3 = 2*cpl_lo(C)+1;
        constexpr int I = N/(D2*D3), J = (N/D3)%D2, K = N%D3;
        constexpr float cgv = CG.v[C][I][J][K];
        if constexpr (cgv != 0.0f){
            constexpr int pidx = TRANS ? (J*D1 + I) : (I*D2 + J);
            if constexpr (N == first_nz_asym(C, K))
                tp[K] = p[pidx] * cgv;                // first term: FMUL-imm
            else
                tp[K] = fmaf(p[pidx], cgv, tp[K]);    // FFMA-imm (rt=1)
        }
        ALoop<C, TRANS, N+1, TOTAL>::run(p, tp);
    }
};
template<int C, bool TRANS, int TOTAL>
struct ALoop<C, TRANS, TOTAL, TOTAL> {
    __device__ __forceinline__ static void run(const float*, float*){}
};

template<int C, int N, int TOTAL>
struct SLoop {
    __device__ __forceinline__ static void run(const float* __restrict__ pu, float* tp){
        constexpr int D = 2*cpl_l1(C)+1, D3 = 2*cpl_lo(C)+1;
        constexpr int t = N/D3, K = N%D3;
        constexpr int I = tri_i(D, t), J = tri_j(D, t);
        constexpr float cgv = cg_symv(C, I, J, K);
        if constexpr (cgv != 0.0f){
            if constexpr (t == first_nz_sym(C, K))
                tp[K] = pu[t] * cgv;
            else
                tp[K] = fmaf(pu[t], cgv, tp[K]);
        }
        SLoop<C, N+1, TOTAL>::run(pu, tp);
    }
};
template<int C, int TOTAL>
struct SLoop<C, TOTAL, TOTAL> {
    __device__ __forceinline__ static void run(const float*, float*){}
};

template<int C, bool SYM, bool INIT, int K, int D3>
struct MixLoop {
    __device__ __forceinline__ static void run(const float* tp, float mixv, float (&acc)[16]){
        constexpr int LO = cpl_lo(C);
        constexpr int BASE = (LO==0) ? 0 : (LO==1) ? 1 : (LO==2) ? 4 : 9;
        constexpr bool anyk = SYM ? (first_nz_sym(C,K) >= 0) : (first_nz_asym(C,K) >= 0);
        if constexpr (anyk){
            if constexpr (INIT) acc[BASE+K] = tp[K] * mixv;
            else                acc[BASE+K] = fmaf(tp[K], mixv, acc[BASE+K]);
        } else if constexpr (INIT){
            acc[BASE+K] = 0.0f;
        }
        MixLoop<C, SYM, INIT, K+1, D3>::run(tp, mixv, acc);
    }
};
template<int C, bool SYM, bool INIT, int D3>
struct MixLoop<C, SYM, INIT, D3, D3> {
    __device__ __forceinline__ static void run(const float*, float, float (&)[16]){}
};

template<int C, bool SYM, bool TRANS, bool INIT>
__device__ __forceinline__ void do_cpl(const float* __restrict__ p,
                                       float mixv,
                                       float (&acc)[16])
{
    constexpr int D3 = 2*cpl_lo(C)+1;
    if constexpr (cpl_any(C, SYM)){
        float tp[D3];
        if constexpr (SYM){
            constexpr int D = 2*cpl_l1(C)+1, TRI = D*(D+1)/2;
            SLoop<C, 0, TRI*D3>::run(p, tp);
        } else {
            constexpr int D1 = 2*cpl_l1(C)+1, D2 = 2*cpl_l2(C)+1;
            ALoop<C, TRANS, 0, D1*D2*D3>::run(p, tp);
        }
        MixLoop<C, SYM, INIT, 0, D3>::run(tp, mixv, acc);
    } else if constexpr (INIT){
        float dummy[1];
        MixLoop<C, SYM, INIT, 0, D3>::run(dummy, 0.0f, acc);
    }
}

// ---------------------------------------------------------------------------
// Hoisted per-channel coefficients (loaded once per block)
// ---------------------------------------------------------------------------
struct Coefs {
    float k0, k1, k2;
    float m0, m1, m2, m34, m6, m7, m912, m10, m11, m13, m14, m15, m16;
};

// ---------------------------------------------------------------------------
// One row: pure register math between LDG (done by caller) and STG.
// ---------------------------------------------------------------------------
__device__ __forceinline__ void compute_row(
    float x0, const float (&x1)[3], const float (&x2)[5],
    const Coefs& cf, float* __restrict__ O)
{
    float acc[16];

    // keep terms
    acc[0] = x0 * cf.k0;
#pragma unroll
    for(int j=0;j<3;j++) acc[1+j] = x1[j] * cf.k1;
#pragma unroll
    for(int j=0;j<5;j++) acc[4+j] = x2[j] * cf.k2;
    // acc[9..15] initialized by coupling 15 (INIT=true)

    // --- l=0 couplings: CG is exactly delta (0.5 folded via h0) ---
    const float h0 = 0.5f * x0;
    acc[0] = fmaf(h0 * cf.m0, x0, acc[0]);                 // (0,0,0)
    {
        const float w1 = h0 * cf.m34;                      // (1,0,1)+(1,1,0)
#pragma unroll
        for(int k=0;k<3;k++) acc[1+k] = fmaf(x1[k], w1, acc[1+k]);
    }
    {
        const float w2 = h0 * cf.m912;                     // (2,0,2)+(2,2,0)
#pragma unroll
        for(int k=0;k<5;k++) acc[4+k] = fmaf(x2[k], w2, acc[4+k]);
    }

    // --- x1 (x) x1 : symmetric fold; (1,1,1) vanishes ---
    {
        float pu[6];
        {
            int t = 0;
#pragma unroll
            for(int i=0;i<3;i++)
#pragma unroll
                for(int j=i;j<3;j++) pu[t++] = x1[i] * x1[j];
        }
        do_cpl<1,  true, false, false>(pu, cf.m1,  acc);   // (0,1,1)
        do_cpl<10, true, false, false>(pu, cf.m10, acc);   // (2,1,1)
    }
    // --- x1 (x) x2 : shared by 6 couplings (3 via transposed view) ---
    {
        float p[15];
#pragma unroll
        for(int i=0;i<3;i++)
#pragma unroll
            for(int j=0;j<5;j++) p[i*5+j] = x1[i] * x2[j];
        do_cpl<6,  false, false, false>(p, cf.m6,  acc);   // (1,1,2)
        do_cpl<11, false, false, false>(p, cf.m11, acc);   // (2,1,2)
        do_cpl<15, false, false, true >(p, cf.m15, acc);   // (3,1,2) INIT lo=3
        do_cpl<7,  false, true,  false>(p, cf.m7,  acc);   // (1,2,1)
        do_cpl<13, false, true,  false>(p, cf.m13, acc);   // (2,2,1)
        do_cpl<16, false, true,  false>(p, cf.m16, acc);   // (3,2,1)
    }
    // --- x2 (x) x2 : symmetric fold; (1,2,2) and (3,2,2) vanish ---
    {
        float pu[15];
        {
            int t = 0;
#pragma unroll
            for(int i=0;i<5;i++)
#pragma unroll
                for(int j=i;j<5;j++) pu[t++] = x2[i] * x2[j];
        }
        do_cpl<2,  true, false, false>(pu, cf.m2,  acc);   // (0,2,2)
        do_cpl<14, true, false, false>(pu, cf.m14, acc);   // (2,2,2)
    }

    // out row layout: lo0 @0, lo1 @128 (3x128), lo2 @512 (5x128), lo3 @1152 (7x128)
    O[0] = acc[0];
#pragma unroll
    for(int k=0;k<3;k++) O[128  + 128*k] = acc[1+k];
#pragma unroll
    for(int k=0;k<5;k++) O[512  + 128*k] = acc[4+k];
#pragma unroll
    for(int k=0;k<7;k++) O[1152 + 128*k] = acc[9+k];
}

// ---------------------------------------------------------------------------
// Grid-stride persistent blocks: 2048 blocks x 8 rows.
// Coefficients load once per block; next row's x prefetches under current
// row's compute -> entry bubble paid once per block instead of once per row.
// ---------------------------------------------------------------------------
__global__ void __launch_bounds__(128, 9) smix_kernel(
    const float* __restrict__ xg,
    const float* __restrict__ keepg,
    const float* __restrict__ mixg,
    float* __restrict__ outg)
{
    const int ch = threadIdx.x;

    // ---- coefficients: once per block ----
    Coefs cf;
    cf.k0  = keepg[ch];
    cf.k1  = keepg[128 + ch];
    cf.k2  = keepg[256 + ch];
    cf.m0  = mixg[ 0*128 + ch];
    cf.m1  = mixg[ 1*128 + ch];
    cf.m2  = mixg[ 2*128 + ch];
    cf.m34 = mixg[ 3*128 + ch] + mixg[ 4*128 + ch];
    cf.m6  = mixg[ 6*128 + ch];
    cf.m7  = mixg[ 7*128 + ch];
    cf.m912= mixg[ 9*128 + ch] + mixg[12*128 + ch];
    cf.m10 = mixg[10*128 + ch];
    cf.m11 = mixg[11*128 + ch];
    cf.m13 = mixg[13*128 + ch];
    cf.m14 = mixg[14*128 + ch];
    cf.m15 = mixg[15*128 + ch];
    cf.m16 = mixg[16*128 + ch];

    int row = blockIdx.x;

    // ---- prologue: load first row ----
    float c0, c1[3], c2[5];
    {
        const float* X = xg + (long)row * 1152 + ch;
        c0 = X[0];
#pragma unroll
        for(int j=0;j<3;j++) c1[j] = X[128 + 128*j];
#pragma unroll
        for(int j=0;j<5;j++) c2[j] = X[512 + 128*j];
    }

#pragma unroll 2
    for(int it = 0; it < RPB; ++it){
        // prefetch next row (last iter reloads same row; result discarded)
        const int nrow = row + ((it + 1 < RPB) ? GRIDB : 0);
        float n0, n1[3], n2[5];
        {
            const float* X = xg + (long)nrow * 1152 + ch;
            n0 = X[0];
#pragma unroll
            for(int j=0;j<3;j++) n1[j] = X[128 + 128*j];
#pragma unroll
            for(int j=0;j<5;j++) n2[j] = X[512 + 128*j];
        }

        // compute current row (covers the prefetch latency)
        compute_row(c0, c1, c2, cf, outg + (long)row * 2048 + ch);

        // rotate
        c0 = n0;
#pragma unroll
        for(int j=0;j<3;j++) c1[j] = n1[j];
#pragma unroll
        for(int j=0;j<5;j++) c2[j] = n2[j];
        row = nrow;
    }
}

// ---------------------------------------------------------------------------
// Launch: single kernel, pointers only -> trivially graph-capturable.
// ---------------------------------------------------------------------------
extern "C" void kernel_launch(void* const* d_in, const int* in_sizes, int n_in,
                              void* d_out, int out_size)
{
    (void)in_sizes; (void)n_in; (void)out_size;
    const float* x    = (const float*)d_in[0];
    const float* keep = (const float*)d_in[1];
    const float* mix  = (const float*)d_in[2];

    smix_kernel<<<GRIDB, 128>>>(x, keep, mix, (float*)d_out);
}

// round 8
// speedup vs baseline: 1.1233x; 1.1233x over previous
#include <cuda_runtime.h>

#define NCH   128
#define BATCH 16384

// ---------------------------------------------------------------------------
// Coupling table (lo, l1, l2) in the reference enumeration order
// ---------------------------------------------------------------------------
__host__ __device__ constexpr int cpl_lo(int c){ constexpr int t[18]={0,0,0,1,1,1,1,1,1,2,2,2,2,2,2,3,3,3}; return t[c]; }
__host__ __device__ constexpr int cpl_l1(int c){ constexpr int t[18]={0,1,2,0,1,1,1,2,2,0,1,1,2,2,2,1,2,2}; return t[c]; }
__host__ __device__ constexpr int cpl_l2(int c){ constexpr int t[18]={0,1,2,1,0,1,2,1,2,2,1,2,0,1,2,2,1,2}; return t[c]; }

// ---------------------------------------------------------------------------
// Compile-time CG table (constexpr port of reference, double precision, 0.5
// folded in). Every nonzero becomes an FFMA/FMUL immediate in SASS.
// ---------------------------------------------------------------------------
__host__ __device__ constexpr double cfabs_c(double x){ return x < 0 ? -x : x; }
__host__ __device__ constexpr double csqrt_c(double x){
    double g = x > 1.0 ? x : 1.0;
    for(int i=0;i<64;i++) g = 0.5*(g + x/g);
    return g;
}
__host__ __device__ constexpr double fct_c(int n){ double r = 1.0; for(int i=2;i<=n;i++) r *= (double)i; return r; }

struct Cplx { double re, im; };
__host__ __device__ constexpr Cplx cmul(Cplx a, Cplx b){ return Cplx{a.re*b.re - a.im*b.im, a.re*b.im + a.im*b.re}; }
__host__ __device__ constexpr Cplx cadd(Cplx a, Cplx b){ return Cplx{a.re + b.re, a.im + b.im}; }
__host__ __device__ constexpr Cplx cconj(Cplx a){ return Cplx{a.re, -a.im}; }
__host__ __device__ constexpr Cplx cscal(double s, Cplx a){ return Cplx{s*a.re, s*a.im}; }

struct CgTable { float v[18][5][5][7]; };

__host__ __device__ constexpr CgTable build_cg_table(){
    CgTable T{};
    for(int c=0;c<18;c++){
        const int lo = cpl_lo(c), l1 = cpl_l1(c), l2 = cpl_l2(c);

        double C[7][7][7] = {};
        {
            double pref_j = csqrt_c((2*lo+1) * fct_c(lo+l1-l2) * fct_c(lo-l1+l2) *
                                    fct_c(l1+l2-lo) / fct_c(l1+l2+lo+1));
            for(int m1=-l1;m1<=l1;m1++){
                for(int m2=-l2;m2<=l2;m2++){
                    int m3 = m1 + m2;
                    if(m3 < -lo || m3 > lo) continue;
                    double pref_m = csqrt_c(fct_c(lo+m3)*fct_c(lo-m3)*fct_c(l1-m1)*
                                            fct_c(l1+m1)*fct_c(l2-m2)*fct_c(l2+m2));
                    double s = 0.0;
                    for(int vv=0; vv<=l1+l2-lo; vv++){
                        int a = l1+l2-lo-vv, b = l1-m1-vv, cc = l2+m2-vv;
                        int d = lo-l2+m1+vv, e = lo-l1-m2+vv;
                        if(a<0 || b<0 || cc<0 || d<0 || e<0) continue;
                        double term = 1.0 / (fct_c(vv)*fct_c(a)*fct_c(b)*fct_c(cc)*fct_c(d)*fct_c(e));
                        s += (vv & 1) ? -term : term;
                    }
                    C[m1+l1][m2+l2][m3+lo] = pref_j * pref_m * s;
                }
            }
        }

        Cplx q[3][7][7] = {};
        const int ls[3] = {l1, l2, lo};
        for(int t=0;t<3;t++){
            const int l = ls[t];
            const double s2 = 1.0 / csqrt_c(2.0);
            for(int m=-l;m<0;m++){
                q[t][l+m][l-m] = Cplx{s2, 0.0};
                q[t][l+m][l+m] = Cplx{0.0, -s2};
            }
            q[t][l][l] = Cplx{1.0, 0.0};
            for(int m=1;m<=l;m++){
                double sg = (m & 1) ? -1.0 : 1.0;
                q[t][l+m][l+m] = Cplx{sg*s2, 0.0};
                q[t][l+m][l-m] = Cplx{0.0, sg*s2};
            }
            Cplx ph = (l==0) ? Cplx{1,0} : (l==1) ? Cplx{0,-1} : (l==2) ? Cplx{-1,0} : Cplx{0,1};
            for(int a=0;a<7;a++) for(int b=0;b<7;b++) q[t][a][b] = cmul(q[t][a][b], ph);
        }

        const int d1 = 2*l1+1, d2 = 2*l2+1, d3 = 2*lo+1;
        double Rre[5][5][7] = {}, Rim[5][5][7] = {};
        double sre = 0.0, sim = 0.0;
        for(int i=0;i<d1;i++)
            for(int j=0;j<d2;j++)
                for(int k=0;k<d3;k++){
                    Cplx s{0.0, 0.0};
                    for(int a=0;a<d1;a++)
                        for(int b=0;b<d2;b++)
                            for(int cc=0;cc<d3;cc++){
                                if(C[a][b][cc] == 0.0) continue;
                                s = cadd(s, cscal(C[a][b][cc],
                                        cmul(cmul(q[0][a][i], q[1][b][j]), cconj(q[2][cc][k]))));
                            }
                    Rre[i][j][k] = s.re; Rim[i][j][k] = s.im;
                    sre += cfabs_c(s.re); sim += cfabs_c(s.im);
                }
        const bool use_re = (sre >= sim);
        for(int i=0;i<d1;i++)
            for(int j=0;j<d2;j++)
                for(int k=0;k<d3;k++){
                    double val = use_re ? Rre[i][j][k] : Rim[i][j][k];
                    T.v[c][i][j][k] = 0.5f * (float)val;
                }
    }
    return T;
}

constexpr CgTable CG = build_cg_table();

// ---------------------------------------------------------------------------
// Compile-time helpers: symmetric folding, first-nonzero detection
// ---------------------------------------------------------------------------
__host__ __device__ constexpr int tri_i(int d, int t){
    int i = 0, rem = t;
    while(rem >= d - i){ rem -= d - i; i++; }
    return i;
}
__host__ __device__ constexpr int tri_j(int d, int t){
    int i = 0, rem = t;
    while(rem >= d - i){ rem -= d - i; i++; }
    return i + rem;
}

__host__ __device__ constexpr float cg_symv(int c, int i, int j, int k){
    return (i == j) ? CG.v[c][i][j][k] : (CG.v[c][i][j][k] + CG.v[c][j][i][k]);
}

__host__ __device__ constexpr int first_nz_asym(int c, int K){
    const int d1 = 2*cpl_l1(c)+1, d2 = 2*cpl_l2(c)+1, d3 = 2*cpl_lo(c)+1;
    for(int i=0;i<d1;i++)
        for(int j=0;j<d2;j++)
            if(CG.v[c][i][j][K] != 0.0f) return (i*d2+j)*d3 + K;
    return -1;
}
__host__ __device__ constexpr int first_nz_sym(int c, int K){
    const int d = 2*cpl_l1(c)+1;
    int t = 0;
    for(int i=0;i<d;i++)
        for(int j=i;j<d;j++,t++)
            if(cg_symv(c,i,j,K) != 0.0f) return t;
    return -1;
}
__host__ __device__ constexpr bool cpl_any(int c, bool sym){
    const int d3 = 2*cpl_lo(c)+1;
    for(int k=0;k<d3;k++)
        if((sym ? first_nz_sym(c,k) : first_nz_asym(c,k)) >= 0) return true;
    return false;
}

// ---------------------------------------------------------------------------
// Unrolled contraction loops (template recursion, all indices compile-time)
// ---------------------------------------------------------------------------
template<int C, bool TRANS, int N, int TOTAL>
struct ALoop {
    __device__ __forceinline__ static void run(const float* __restrict__ p, float* tp){
        constexpr int D1 = 2*cpl_l1(C)+1, D2 = 2*cpl_l2(C)+1, D3 = 2*cpl_lo(C)+1;
        constexpr int I = N/(D2*D3), J = (N/D3)%D2, K = N%D3;
        constexpr float cgv = CG.v[C][I][J][K];
        if constexpr (cgv != 0.0f){
            constexpr int pidx = TRANS ? (J*D1 + I) : (I*D2 + J);
            if constexpr (N == first_nz_asym(C, K))
                tp[K] = p[pidx] * cgv;                // first term: FMUL-imm
            else
                tp[K] = fmaf(p[pidx], cgv, tp[K]);    // FFMA-imm (rt=1)
        }
        ALoop<C, TRANS, N+1, TOTAL>::run(p, tp);
    }
};
template<int C, bool TRANS, int TOTAL>
struct ALoop<C, TRANS, TOTAL, TOTAL> {
    __device__ __forceinline__ static void run(const float*, float*){}
};

template<int C, int N, int TOTAL>
struct SLoop {
    __device__ __forceinline__ static void run(const float* __restrict__ pu, float* tp){
        constexpr int D = 2*cpl_l1(C)+1, D3 = 2*cpl_lo(C)+1;
        constexpr int t = N/D3, K = N%D3;
        constexpr int I = tri_i(D, t), J = tri_j(D, t);
        constexpr float cgv = cg_symv(C, I, J, K);
        if constexpr (cgv != 0.0f){
            if constexpr (t == first_nz_sym(C, K))
                tp[K] = pu[t] * cgv;
            else
                tp[K] = fmaf(pu[t], cgv, tp[K]);
        }
        SLoop<C, N+1, TOTAL>::run(pu, tp);
    }
};
template<int C, int TOTAL>
struct SLoop<C, TOTAL, TOTAL> {
    __device__ __forceinline__ static void run(const float*, float*){}
};

template<int C, bool SYM, bool INIT, int K, int D3>
struct MixLoop {
    __device__ __forceinline__ static void run(const float* tp, float mixv, float (&acc)[16]){
        constexpr int LO = cpl_lo(C);
        constexpr int BASE = (LO==0) ? 0 : (LO==1) ? 1 : (LO==2) ? 4 : 9;
        constexpr bool anyk = SYM ? (first_nz_sym(C,K) >= 0) : (first_nz_asym(C,K) >= 0);
        if constexpr (anyk){
            if constexpr (INIT) acc[BASE+K] = tp[K] * mixv;
            else                acc[BASE+K] = fmaf(tp[K], mixv, acc[BASE+K]);
        } else if constexpr (INIT){
            acc[BASE+K] = 0.0f;
        }
        MixLoop<C, SYM, INIT, K+1, D3>::run(tp, mixv, acc);
    }
};
template<int C, bool SYM, bool INIT, int D3>
struct MixLoop<C, SYM, INIT, D3, D3> {
    __device__ __forceinline__ static void run(const float*, float, float (&)[16]){}
};

template<int C, bool SYM, bool TRANS, bool INIT>
__device__ __forceinline__ void do_cpl(const float* __restrict__ p,
                                       float mixv,
                                       float (&acc)[16])
{
    constexpr int D3 = 2*cpl_lo(C)+1;
    if constexpr (cpl_any(C, SYM)){
        float tp[D3];
        if constexpr (SYM){
            constexpr int D = 2*cpl_l1(C)+1, TRI = D*(D+1)/2;
            SLoop<C, 0, TRI*D3>::run(p, tp);
        } else {
            constexpr int D1 = 2*cpl_l1(C)+1, D2 = 2*cpl_l2(C)+1;
            ALoop<C, TRANS, 0, D1*D2*D3>::run(p, tp);
        }
        MixLoop<C, SYM, INIT, 0, D3>::run(tp, mixv, acc);
    } else if constexpr (INIT){
        float dummy[1];
        MixLoop<C, SYM, INIT, 0, D3>::run(dummy, 0.0f, acc);
    }
}

// ---------------------------------------------------------------------------
// Kernel: 128 threads/block = 1 row; 1 channel per thread; no shared memory.
// Streaming hints on the x / out streams (no reuse); coefficient reads use
// the default path (reused by all 16384 blocks -> L2-resident).
// ---------------------------------------------------------------------------
__global__ void __launch_bounds__(128, 12) smix_kernel(
    const float* __restrict__ xg,
    const float* __restrict__ keepg,
    const float* __restrict__ mixg,
    float* __restrict__ outg)
{
    const int ch  = threadIdx.x;
    const long row = blockIdx.x;

    const float* X = xg + row * 1152 + ch;

    // streaming loads: x row is touched exactly once
    float x0 = __ldcs(X);
    float x1[3];
#pragma unroll
    for(int j=0;j<3;j++) x1[j] = __ldcs(X + 128 + 128*j);
    float x2[5];
#pragma unroll
    for(int j=0;j<5;j++) x2[j] = __ldcs(X + 512 + 128*j);

    // accumulators: lo=0 -> acc[0]; lo=1 -> acc[1..3]; lo=2 -> acc[4..8]; lo=3 -> acc[9..15]
    float acc[16];

    // keep terms
    acc[0] = x0 * keepg[ch];
    {
        const float kc1 = keepg[128 + ch];
#pragma unroll
        for(int j=0;j<3;j++) acc[1+j] = x1[j] * kc1;
    }
    {
        const float kc2 = keepg[256 + ch];
#pragma unroll
        for(int j=0;j<5;j++) acc[4+j] = x2[j] * kc2;
    }
    // acc[9..15] initialized by coupling 15 (INIT=true)

    // --- l=0 couplings: CG is exactly delta (0.5 folded via h0) ---
    const float h0 = 0.5f * x0;
    acc[0] = fmaf(h0 * mixg[0*128 + ch], x0, acc[0]);             // (0,0,0)
    {
        const float w1 = h0 * (mixg[3*128 + ch] + mixg[4*128 + ch]);   // (1,0,1)+(1,1,0)
#pragma unroll
        for(int k=0;k<3;k++) acc[1+k] = fmaf(x1[k], w1, acc[1+k]);
    }
    {
        const float w2 = h0 * (mixg[9*128 + ch] + mixg[12*128 + ch]);  // (2,0,2)+(2,2,0)
#pragma unroll
        for(int k=0;k<5;k++) acc[4+k] = fmaf(x2[k], w2, acc[4+k]);
    }

    // --- x1 (x) x1 : symmetric fold; (1,1,1) vanishes ---
    {
        float pu[6];
        {
            int t = 0;
#pragma unroll
            for(int i=0;i<3;i++)
#pragma unroll
                for(int j=i;j<3;j++) pu[t++] = x1[i] * x1[j];
        }
        do_cpl<1,  true, false, false>(pu, mixg[ 1*128 + ch], acc);   // (0,1,1)
        do_cpl<10, true, false, false>(pu, mixg[10*128 + ch], acc);   // (2,1,1)
    }
    // --- x1 (x) x2 : shared by 6 couplings (3 via transposed view) ---
    {
        float p[15];
#pragma unroll
        for(int i=0;i<3;i++)
#pragma unroll
            for(int j=0;j<5;j++) p[i*5+j] = x1[i] * x2[j];
        do_cpl<6,  false, false, false>(p, mixg[ 6*128 + ch], acc);   // (1,1,2)
        do_cpl<11, false, false, false>(p, mixg[11*128 + ch], acc);   // (2,1,2)
        do_cpl<15, false, false, true >(p, mixg[15*128 + ch], acc);   // (3,1,2) INIT lo=3
        do_cpl<7,  false, true,  false>(p, mixg[ 7*128 + ch], acc);   // (1,2,1)
        do_cpl<13, false, true,  false>(p, mixg[13*128 + ch], acc);   // (2,2,1)
        do_cpl<16, false, true,  false>(p, mixg[16*128 + ch], acc);   // (3,2,1)
    }
    // --- x2 (x) x2 : symmetric fold; (1,2,2) and (3,2,2) vanish ---
    {
        float pu[15];
        {
            int t = 0;
#pragma unroll
            for(int i=0;i<5;i++)
#pragma unroll
                for(int j=i;j<5;j++) pu[t++] = x2[i] * x2[j];
        }
        do_cpl<2,  true, false, false>(pu, mixg[ 2*128 + ch], acc);   // (0,2,2)
        do_cpl<14, true, false, false>(pu, mixg[14*128 + ch], acc);   // (2,2,2)
    }

    // streaming stores: out row is written exactly once, never re-read
    // layout: lo0 @0, lo1 @128 (3x128), lo2 @512 (5x128), lo3 @1152 (7x128)
    float* O = outg + row * 2048 + ch;
    __stcs(O, acc[0]);
#pragma unroll
    for(int k=0;k<3;k++) __stcs(O + 128  + 128*k, acc[1+k]);
#pragma unroll
    for(int k=0;k<5;k++) __stcs(O + 512  + 128*k, acc[4+k]);
#pragma unroll
    for(int k=0;k<7;k++) __stcs(O + 1152 + 128*k, acc[9+k]);
}

// ---------------------------------------------------------------------------
// Launch: single kernel, pointers only -> trivially graph-capturable.
// ---------------------------------------------------------------------------
extern "C" void kernel_launch(void* const* d_in, const int* in_sizes, int n_in,
                              void* d_out, int out_size)
{
    (void)in_sizes; (void)n_in; (void)out_size;
    const float* x    = (const float*)d_in[0];
    const float* keep = (const float*)d_in[1];
    const float* mix  = (const float*)d_in[2];

    smix_kernel<<<BATCH, 128>>>(x, keep, mix, (float*)d_out);
}